// round 4
// baseline (speedup 1.0000x reference)
#include <cuda_runtime.h>

// Problem constants (fixed by setup_inputs)
#define N_PTS 2048
#define N_C   1024
#define B_SZ  8
#define WARPS_PER_BLOCK 8
#define BLOCK_THREADS   256
#define CHUNKS_PER_BATCH (N_PTS / WARPS_PER_BLOCK)        // 256
#define NUM_BLOCKS (B_SZ * CHUNKS_PER_BATCH)              // 2048
#define N_TOTAL (B_SZ * N_PTS)                            // 16384

// Output layout (tuple concat): y_diff | x_diff | d_out(B,N,2) | x_n | y_n
#define OFF_YDIFF 0
#define OFF_XDIFF (N_TOTAL)
#define OFF_DOUT  (2 * N_TOTAL)
#define OFF_XN    (4 * N_TOTAL)
#define OFF_YN    (5 * N_TOTAL)

// Deterministic reduction scratch (no device allocation allowed)
__device__ double g_psum[NUM_BLOCKS];
__device__ double g_psum2[NUM_BLOCKS];
__device__ int    g_count = 0;

typedef unsigned long long ull;

static __device__ __forceinline__ ull u64min(ull a, ull b) { return a < b ? a : b; }
static __device__ __forceinline__ ull u64max(ull a, ull b) { return a > b ? a : b; }

// Branch-free top-2 update (value-only compare; ascending-j order + strict '<'
// keeps earliest index on exact ties within a chain).
static __device__ __forceinline__ void top2_upd(
    float v, int j, float& v1, int& i1, float& v2, int& i2)
{
    const bool b1 = v < v1;
    const bool b2 = v < v2;
    i2 = b1 ? i1 : (b2 ? j : i2);
    v2 = b1 ? v1 : (b2 ? v : v2);
    i1 = b1 ? j : i1;
    v1 = b1 ? v : v1;
}

// Merge two sorted top-2 u64-key pairs.
static __device__ __forceinline__ void merge2(ull& a1, ull& a2, ull b1, ull b2)
{
    ull n1 = u64min(a1, b1);
    ull n2 = u64min(u64max(a1, b1), u64min(a2, b2));
    a1 = n1; a2 = n2;
}

static __device__ __forceinline__ ull mkkey(float v, int i)
{
    return ((ull)__float_as_uint(v) << 32) | (unsigned int)i;
}

// Fused kernel: NN search + derivative + outputs + deterministic BN (last-block pattern).
__global__ __launch_bounds__(BLOCK_THREADS) void nn_fused_kernel(
    const float* __restrict__ y, const float* __restrict__ x,
    const float* __restrict__ bn_w, const float* __restrict__ bn_b,
    float* __restrict__ out)
{
    __shared__ float  sx[N_PTS];
    __shared__ float  sy[N_PTS];
    __shared__ float  s_d2[WARPS_PER_BLOCK];
    __shared__ double s_red[2 * BLOCK_THREADS];
    __shared__ float  s_affine[2];
    __shared__ int    s_islast;

    const int b      = blockIdx.x >> 8;       // / CHUNKS_PER_BATCH
    const int chunk  = blockIdx.x & 255;
    const int warpId = threadIdx.x >> 5;
    const int lane   = threadIdx.x & 31;
    const int p      = chunk * WARPS_PER_BLOCK + warpId;   // point index within batch

    // Vectorized smem fill
    {
        const float4* xb4 = (const float4*)(x + b * N_PTS);
        const float4* yb4 = (const float4*)(y + b * N_PTS);
        float4* sxv = (float4*)sx;
        float4* syv = (float4*)sy;
        #pragma unroll
        for (int i = threadIdx.x; i < N_PTS / 4; i += BLOCK_THREADS) {
            sxv[i] = xb4[i];
            syv[i] = yb4[i];
        }
    }
    __syncthreads();

    // Candidate set: context points search context only; target p searches j <= p.
    const int nCand = (p < N_C) ? N_C : (p + 1);
    const float xi = sx[p];

    const float INF = __int_as_float(0x7f800000);
    // 4 independent top-2 chains (one per float4 slot) -> ILP across the selects.
    float a1 = INF, a2 = INF, b1v = INF, b2v = INF;
    float c1 = INF, c2 = INF, e1 = INF, e2 = INF;
    int   ai1 = 0x7fffffff, ai2 = 0x7fffffff, bi1 = 0x7fffffff, bi2 = 0x7fffffff;
    int   ci1 = 0x7fffffff, ci2 = 0x7fffffff, ei1 = 0x7fffffff, ei2 = 0x7fffffff;

    const float4* sx4 = (const float4*)sx;
    const int nFull = nCand >> 7;                     // groups of 128 (32 lanes x 4)
    for (int g = 0; g < nFull; ++g) {
        const int j = (g << 7) + (lane << 2);
        const float4 xs = sx4[(g << 5) + lane];
        const float d0 = xi - xs.x, d1 = xi - xs.y, d2 = xi - xs.z, d3 = xi - xs.w;
        top2_upd(d0 * d0, j,     a1,  ai1, a2,  ai2);
        top2_upd(d1 * d1, j + 1, b1v, bi1, b2v, bi2);
        top2_upd(d2 * d2, j + 2, c1,  ci1, c2,  ci2);
        top2_upd(d3 * d3, j + 3, e1,  ei1, e2,  ei2);
    }
    // Remainder (indices all larger than main-loop ones; chain-local stability ok).
    for (int j = (nFull << 7) + lane; j < nCand; j += 32) {
        const float dx = xi - sx[j];
        top2_upd(dx * dx, j, a1, ai1, a2, ai2);
    }

    // Merge the 4 chains with exact lexicographic (dist,idx) keys.
    ull kA1 = mkkey(a1, ai1),  kA2 = mkkey(a2, ai2);
    ull kB1 = mkkey(b1v, bi1), kB2 = mkkey(b2v, bi2);
    ull kC1 = mkkey(c1, ci1),  kC2 = mkkey(c2, ci2);
    ull kE1 = mkkey(e1, ei1),  kE2 = mkkey(e2, ei2);
    merge2(kA1, kA2, kB1, kB2);
    merge2(kC1, kC2, kE1, kE2);
    merge2(kA1, kA2, kC1, kC2);

    // Cross-lane tournament.
    #pragma unroll
    for (int off = 16; off > 0; off >>= 1) {
        ull o1 = __shfl_down_sync(0xffffffffu, kA1, off);
        ull o2 = __shfl_down_sync(0xffffffffu, kA2, off);
        merge2(kA1, kA2, o1, o2);
    }

    if (lane == 0) {
        const int nn = (int)(unsigned int)(kA2 & 0xffffffffULL);  // argsort[...,1]
        const float xcl  = sx[nn];
        const float ycl  = sy[nn];
        const float xrep = xi - xcl;
        const float yrep = sy[p] - ycl;
        const float nrm  = __fsqrt_rn(__fmul_rn(xrep, xrep));  // exact reference norm
        const float d    = __fdiv_rn(yrep, __fadd_rn(2e-6f, nrm));
        const bool  clip = (fabsf(d) > 200.0f);
        const float d2   = clip ? 0.0f : d;   // d_2 (d_1 == d: NaN impossible here)
        const float lab  = clip ? 0.0f : 1.0f;

        const int g = b * N_PTS + p;
        out[OFF_YDIFF + g]        = yrep;
        out[OFF_XDIFF + g]        = xrep;
        out[OFF_DOUT + 2 * g]     = d2;    // raw; normalized in-place below
        out[OFF_DOUT + 2 * g + 1] = lab;
        out[OFF_XN + g]           = xcl;
        out[OFF_YN + g]           = ycl;
        s_d2[warpId] = d2;
    }
    __syncthreads();

    // Per-block deterministic partial sums, then last-block-done handshake.
    if (threadIdx.x == 0) {
        double s = 0.0, s2 = 0.0;
        #pragma unroll
        for (int w = 0; w < WARPS_PER_BLOCK; w++) {
            double v = (double)s_d2[w];
            s += v; s2 += v * v;
        }
        g_psum[blockIdx.x]  = s;
        g_psum2[blockIdx.x] = s2;
        __threadfence();
        const int old = atomicAdd(&g_count, 1);
        s_islast = (old == NUM_BLOCKS - 1);
    }
    __syncthreads();

    if (!s_islast) return;

    // ---- Last block: final reduce + affine + in-place normalize ----
    __threadfence();  // acquire all other blocks' out[] and psum writes

    {
        double s = 0.0, s2 = 0.0;
        #pragma unroll
        for (int i = threadIdx.x; i < NUM_BLOCKS; i += BLOCK_THREADS) {
            s  += g_psum[i];
            s2 += g_psum2[i];
        }
        s_red[threadIdx.x]                 = s;
        s_red[BLOCK_THREADS + threadIdx.x] = s2;
    }
    __syncthreads();
    #pragma unroll
    for (int off = BLOCK_THREADS / 2; off > 0; off >>= 1) {
        if (threadIdx.x < off) {
            s_red[threadIdx.x]                 += s_red[threadIdx.x + off];
            s_red[BLOCK_THREADS + threadIdx.x] += s_red[BLOCK_THREADS + threadIdx.x + off];
        }
        __syncthreads();
    }
    if (threadIdx.x == 0) {
        const double n    = (double)N_TOTAL;
        const double mean = s_red[0] / n;
        const double var  = s_red[BLOCK_THREADS] / n - mean * mean;
        const double inv  = 1.0 / sqrt(var + 1e-5);
        const float scale = (float)inv * bn_w[0];
        s_affine[0] = scale;
        s_affine[1] = bn_b[0] - (float)mean * scale;
        g_count = 0;   // reset for next graph replay
    }
    __syncthreads();

    const float scale = s_affine[0];
    const float shift = s_affine[1];
    #pragma unroll
    for (int g = threadIdx.x; g < N_TOTAL; g += BLOCK_THREADS) {
        const int idx = OFF_DOUT + 2 * g;
        out[idx] = fmaf(out[idx], scale, shift);
    }
}

extern "C" void kernel_launch(void* const* d_in, const int* in_sizes, int n_in,
                              void* d_out, int out_size) {
    const float* y    = (const float*)d_in[0];
    const float* x    = (const float*)d_in[1];
    const float* bn_w = (const float*)d_in[2];
    const float* bn_b = (const float*)d_in[3];
    float* out = (float*)d_out;

    nn_fused_kernel<<<NUM_BLOCKS, BLOCK_THREADS>>>(y, x, bn_w, bn_b, out);
}

// round 6
// speedup vs baseline: 1.0707x; 1.0707x over previous
#include <cuda_runtime.h>

// Problem constants (fixed by setup_inputs)
#define N_PTS 2048
#define N_C   1024
#define B_SZ  8
#define BLOCK_THREADS 256
#define PTS_PER_BLOCK 256
#define BLOCKS_PER_BATCH (N_PTS / PTS_PER_BLOCK)   // 8
#define NUM_BLOCKS (B_SZ * BLOCKS_PER_BATCH)       // 64
#define N_TOTAL (B_SZ * N_PTS)                     // 16384
#define NB 512                                     // bins per batch

// Output layout (tuple concat): y_diff | x_diff | d_out(B,N,2) | x_n | y_n
#define OFF_YDIFF 0
#define OFF_XDIFF (N_TOTAL)
#define OFF_DOUT  (2 * N_TOTAL)
#define OFF_XN    (4 * N_TOTAL)
#define OFF_YN    (5 * N_TOTAL)

__device__ double g_psum[NUM_BLOCKS];
__device__ double g_psum2[NUM_BLOCKS];
__device__ int    g_count = 0;

typedef unsigned long long ull;

static __device__ __forceinline__ int bin_of(float v, float xmin, float inv) {
    int t = (int)((v - xmin) * inv);
    t = t < 0 ? 0 : t;
    return t > (NB - 1) ? (NB - 1) : t;
}

__global__ __launch_bounds__(BLOCK_THREADS) void nn_bin_kernel(
    const float* __restrict__ y, const float* __restrict__ x,
    const float* __restrict__ bn_w, const float* __restrict__ bn_b,
    float* __restrict__ out)
{
    __shared__ float  sx[N_PTS];
    __shared__ float  sy[N_PTS];
    __shared__ float  bx[N_PTS];      // x values in bin order
    __shared__ int    bidx[N_PTS];    // original indices in bin order
    __shared__ int    binCnt[NB];
    __shared__ int    binStart[NB + 1];
    __shared__ int    binFill[NB];
    __shared__ int    scanBuf[BLOCK_THREADS];
    __shared__ float  s_mnmx[16];
    __shared__ float  s_minmax[2];
    __shared__ double s_red[2 * BLOCK_THREADS];
    __shared__ float  s_affine[2];
    __shared__ int    s_islast;

    const int tid   = threadIdx.x;
    const int wid   = tid >> 5;
    const int lane  = tid & 31;
    const int batch = blockIdx.x / BLOCKS_PER_BATCH;
    const int base  = (blockIdx.x % BLOCKS_PER_BATCH) * PTS_PER_BLOCK;

    // ---- Load batch into SMEM (vectorized) ----
    {
        const float4* xb4 = (const float4*)(x + batch * N_PTS);
        const float4* yb4 = (const float4*)(y + batch * N_PTS);
        float4* sxv = (float4*)sx;
        float4* syv = (float4*)sy;
        #pragma unroll
        for (int i = tid; i < N_PTS / 4; i += BLOCK_THREADS) {
            sxv[i] = xb4[i];
            syv[i] = yb4[i];
        }
    }
    // Zero histogram while loads land
    #pragma unroll
    for (int i = tid; i < NB; i += BLOCK_THREADS) binCnt[i] = 0;
    __syncthreads();

    // ---- Per-batch min/max of x ----
    {
        float mn = __int_as_float(0x7f800000);
        float mx = -mn;
        #pragma unroll
        for (int i = tid; i < N_PTS; i += BLOCK_THREADS) {
            float v = sx[i];
            mn = fminf(mn, v);
            mx = fmaxf(mx, v);
        }
        #pragma unroll
        for (int off = 16; off > 0; off >>= 1) {
            mn = fminf(mn, __shfl_down_sync(0xffffffffu, mn, off));
            mx = fmaxf(mx, __shfl_down_sync(0xffffffffu, mx, off));
        }
        if (lane == 0) { s_mnmx[wid] = mn; s_mnmx[8 + wid] = mx; }
        __syncthreads();
        if (tid == 0) {
            float m0 = s_mnmx[0], m1 = s_mnmx[8];
            #pragma unroll
            for (int w = 1; w < 8; w++) {
                m0 = fminf(m0, s_mnmx[w]);
                m1 = fmaxf(m1, s_mnmx[8 + w]);
            }
            s_minmax[0] = m0;
            s_minmax[1] = m1;
        }
        __syncthreads();
    }
    const float xmin  = s_minmax[0];
    const float range = fmaxf(s_minmax[1] - xmin, 1e-20f);
    const float inv   = (float)NB / range;
    const float width = range / (float)NB;

    // ---- Histogram ----
    #pragma unroll
    for (int i = tid; i < N_PTS; i += BLOCK_THREADS)
        atomicAdd(&binCnt[bin_of(sx[i], xmin, inv)], 1);
    __syncthreads();

    // ---- Exclusive scan over NB=512 bins (256 threads x 2 bins each) ----
    {
        const int c0 = binCnt[2 * tid];
        const int c1 = binCnt[2 * tid + 1];
        const int s  = c0 + c1;
        scanBuf[tid] = s;
        __syncthreads();
        #pragma unroll
        for (int off = 1; off < BLOCK_THREADS; off <<= 1) {
            int v = (tid >= off) ? scanBuf[tid - off] : 0;
            __syncthreads();
            scanBuf[tid] += v;
            __syncthreads();
        }
        const int excl = scanBuf[tid] - s;
        binStart[2 * tid]     = excl;
        binStart[2 * tid + 1] = excl + c0;
        binFill[2 * tid]      = excl;
        binFill[2 * tid + 1]  = excl + c0;
        if (tid == BLOCK_THREADS - 1) binStart[NB] = scanBuf[tid];
        __syncthreads();
    }

    // ---- Scatter (counting sort by bin) ----
    #pragma unroll
    for (int i = tid; i < N_PTS; i += BLOCK_THREADS) {
        const float v = sx[i];
        const int   t = bin_of(v, xmin, inv);
        const int pos = atomicAdd(&binFill[t], 1);
        bx[pos]   = v;
        bidx[pos] = i;
    }
    __syncthreads();

    // ---- Per-thread NN search over expanding bin window ----
    const int   p     = base + tid;                    // point index within batch
    const int   limit = (p < N_C) ? (N_C - 1) : p;     // valid candidate: j <= limit
    const float xi    = sx[p];

    // top-2 by exact key = (bits(sqrt_rn(dx*dx)) << 32) | j ; init to (+inf, maxidx)
    const ull KEY_INF = ((ull)0x7f800000u << 32) | 0xffffffffu;
    ull k1 = KEY_INF, k2 = KEY_INF;

    const int t0 = bin_of(xi, xmin, inv);

    // scan a bin
    #define SCAN_BIN(T)                                                        \
        {                                                                      \
            const int qe = binStart[(T) + 1];                                  \
            for (int q = binStart[(T)]; q < qe; ++q) {                         \
                const int j = bidx[q];                                         \
                if (j <= limit) {                                              \
                    const float dx   = xi - bx[q];                             \
                    const float dist = __fsqrt_rn(__fmul_rn(dx, dx));          \
                    const ull key = ((ull)__float_as_uint(dist) << 32)         \
                                    | (unsigned int)j;                         \
                    if (key < k1)      { k2 = k1; k1 = key; }                  \
                    else if (key < k2) { k2 = key; }                           \
                }                                                              \
            }                                                                  \
        }

    SCAN_BIN(t0);
    {
        int l = t0 - 1, r = t0 + 1;
        while (true) {
            const float d2v = __uint_as_float((unsigned int)(k2 >> 32)); // +inf until 2 found
            // conservative cushion: covers bin-assignment rounding + sqrt rounding ties
            const float thr = d2v + (width * 1e-3f + d2v * 1e-5f);
            const float bl = (l >= 0) ? fmaxf(xi - (xmin + (float)(l + 1) * width), 0.0f)
                                      : __int_as_float(0x7f800000);
            const float br = (r < NB) ? fmaxf((xmin + (float)r * width) - xi, 0.0f)
                                      : __int_as_float(0x7f800000);
            const bool canL = (l >= 0) && (bl <= thr);
            const bool canR = (r < NB) && (br <= thr);
            if (!canL && !canR) break;
            if (canL && (!canR || bl <= br)) { SCAN_BIN(l); --l; }
            else                             { SCAN_BIN(r); ++r; }
        }
    }
    #undef SCAN_BIN

    // ---- Derivative + outputs ----
    float d2out;
    {
        const int nn = (int)(unsigned int)(k2 & 0xffffffffULL);  // argsort[...,1]
        const float xcl  = sx[nn];
        const float ycl  = sy[nn];
        const float xrep = xi - xcl;
        const float yrep = sy[p] - ycl;
        const float nrm  = __fsqrt_rn(__fmul_rn(xrep, xrep));
        const float d    = __fdiv_rn(yrep, __fadd_rn(2e-6f, nrm));
        const bool  clip = (fabsf(d) > 200.0f);
        d2out = clip ? 0.0f : d;
        const float lab = clip ? 0.0f : 1.0f;

        const int g = batch * N_PTS + p;
        out[OFF_YDIFF + g]        = yrep;
        out[OFF_XDIFF + g]        = xrep;
        out[OFF_DOUT + 2 * g]     = d2out;   // raw; normalized in-place below
        out[OFF_DOUT + 2 * g + 1] = lab;
        out[OFF_XN + g]           = xcl;
        out[OFF_YN + g]           = ycl;
    }

    // ---- Deterministic per-block partial sums (fixed tree order) ----
    {
        const double v = (double)d2out;
        s_red[tid]                 = v;
        s_red[BLOCK_THREADS + tid] = v * v;
    }
    __syncthreads();
    #pragma unroll
    for (int off = BLOCK_THREADS / 2; off > 0; off >>= 1) {
        if (tid < off) {
            s_red[tid]                 += s_red[tid + off];
            s_red[BLOCK_THREADS + tid] += s_red[BLOCK_THREADS + tid + off];
        }
        __syncthreads();
    }
    if (tid == 0) {
        g_psum[blockIdx.x]  = s_red[0];
        g_psum2[blockIdx.x] = s_red[BLOCK_THREADS];
        __threadfence();
        const int old = atomicAdd(&g_count, 1);
        s_islast = (old == NUM_BLOCKS - 1);
    }
    __syncthreads();

    if (!s_islast) return;

    // ---- Last block: final reduce + affine + in-place normalize ----
    __threadfence();  // acquire all other blocks' out[] and psum writes

    {
        double s = 0.0, s2 = 0.0;
        if (tid < NUM_BLOCKS) { s = g_psum[tid]; s2 = g_psum2[tid]; }
        s_red[tid]                 = s;
        s_red[BLOCK_THREADS + tid] = s2;
    }
    __syncthreads();
    #pragma unroll
    for (int off = BLOCK_THREADS / 2; off > 0; off >>= 1) {
        if (tid < off) {
            s_red[tid]                 += s_red[tid + off];
            s_red[BLOCK_THREADS + tid] += s_red[BLOCK_THREADS + tid + off];
        }
        __syncthreads();
    }
    if (tid == 0) {
        const double n    = (double)N_TOTAL;
        const double mean = s_red[0] / n;
        const double var  = s_red[BLOCK_THREADS] / n - mean * mean;
        const double invs = 1.0 / sqrt(var + 1e-5);
        const float scale = (float)invs * bn_w[0];
        s_affine[0] = scale;
        s_affine[1] = bn_b[0] - (float)mean * scale;
        g_count = 0;   // reset for next graph replay
    }
    __syncthreads();

    const float scale = s_affine[0];
    const float shift = s_affine[1];
    #pragma unroll
    for (int g = tid; g < N_TOTAL; g += BLOCK_THREADS) {
        const int idx = OFF_DOUT + 2 * g;
        out[idx] = fmaf(out[idx], scale, shift);
    }
}

extern "C" void kernel_launch(void* const* d_in, const int* in_sizes, int n_in,
                              void* d_out, int out_size) {
    const float* y    = (const float*)d_in[0];
    const float* x    = (const float*)d_in[1];
    const float* bn_w = (const float*)d_in[2];
    const float* bn_b = (const float*)d_in[3];
    float* out = (float*)d_out;

    nn_bin_kernel<<<NUM_BLOCKS, BLOCK_THREADS>>>(y, x, bn_w, bn_b, out);
}